// round 13
// baseline (speedup 1.0000x reference)
#include <cuda_runtime.h>

#define NTH 256
#define BT  32
typedef unsigned long long ULL;

#define F2(a, b, c) asm("fma.rn.f32x2 %0, %1, %2, %0;" : "+l"(a) : "l"(b), "l"(c))

// Pre-transposed big weights: [k (128)][j (512)]; threads do LDG.64 at (j, j+1).
// m: 0 enc_Whh0, 1 enc_Wih1, 2 enc_Whh1, 3 dec_Whh0, 4 dec_Wih1, 5 dec_Whh1
__device__ float g_WT[6][128 * 512];
// Aux floats (5120):
//   [e*1536 + kin*512 + j]        = Wih0_e[j][kin]   (e: 0 enc, 1 dec)
//   [3072 + e*1024 + l*512 + j]   = b_e_l[j]
__device__ float g_AUX[5120];

__global__ void prep_w(const float* __restrict__ eWhh0, const float* __restrict__ eWih1,
                       const float* __restrict__ eWhh1, const float* __restrict__ dWhh0,
                       const float* __restrict__ dWih1, const float* __restrict__ dWhh1,
                       const float* __restrict__ eWih0, const float* __restrict__ dWih0,
                       const float* __restrict__ eb0,   const float* __restrict__ eb1,
                       const float* __restrict__ db0,   const float* __restrict__ db1)
{
    int idx = blockIdx.x * blockDim.x + threadIdx.x;
    if (idx < 6 * 65536) {
        int m = idx >> 16;
        int r = idx & 65535;
        int j = r >> 7;       // 0..511
        int k = r & 127;      // 0..127
        const float* src;
        switch (m) {
            case 0: src = eWhh0; break;
            case 1: src = eWih1; break;
            case 2: src = eWhh1; break;
            case 3: src = dWhh0; break;
            case 4: src = dWih1; break;
            default: src = dWhh1; break;
        }
        g_WT[m][k * 512 + j] = src[j * 128 + k];
    } else if (idx < 6 * 65536 + 5120) {
        int i2 = idx - 6 * 65536;
        float v;
        if (i2 < 3072) {
            int e = i2 / 1536;
            int rem = i2 % 1536;
            int kin = rem / 512;
            int j = rem % 512;
            v = (e ? dWih0 : eWih0)[j * 3 + kin];
        } else {
            int i3 = i2 - 3072;
            int e = i3 / 1024;
            int rem = i3 % 1024;
            int layer = rem / 512;
            int j = rem % 512;
            const float* b = e ? (layer ? db1 : db0) : (layer ? eb1 : eb0);
            v = b[j];
        }
        g_AUX[i2] = v;
    }
}

struct SM {
    float2 h0d[128 * 34];   // [k][row] {h,h} duplicated; row stride 34 (even -> 16B align)
    float2 h1d[128 * 34];
    float  c0[32 * 128];    // [row][hh]
    float  c1[32 * 128];
    float  xcur[32 * 4];
    float  fcWs[6 * 128];
    float  fcbs[8];
};

__device__ __forceinline__ float2 up2(ULL v) {
    float2 f;
    asm("mov.b64 {%0, %1}, %2;" : "=f"(f.x), "=f"(f.y) : "l"(v));
    return f;
}
__device__ __forceinline__ ULL pkdup(float v) {
    ULL r;
    asm("mov.b64 %0, {%1, %1};" : "=l"(r) : "f"(v));
    return r;
}
__device__ __forceinline__ float tfast(float x) {
    float y;
    asm("tanh.approx.f32 %0, %1;" : "=f"(y) : "f"(x));
    return y;
}
__device__ __forceinline__ float sigm(float x) {
    return fmaf(0.5f, tfast(0.5f * x), 0.5f);
}

// acc[g*8 + r]: f32x2 lanes = gate outputs (hh0, hh0+1), gate block g, row r0+r.
// Inner body per k: 4x LDG.64 (weights, coalesced) + 4x LDS.128 (h, warp-uniform
// broadcast, pre-duplicated pairs) + 32x FFMA2.
__device__ __forceinline__ void mv128(const float* __restrict__ WT,
                                      const float2* __restrict__ Hd,
                                      int r0, int hh0, ULL* acc)
{
    const float* wp = WT + hh0;
#pragma unroll 2
    for (int k = 0; k < 128; ++k) {
        const float* wk = wp + k * 512;
        ULL w0 = *(const ULL*)(wk);
        ULL w1 = *(const ULL*)(wk + 128);
        ULL w2 = *(const ULL*)(wk + 256);
        ULL w3 = *(const ULL*)(wk + 384);
        const ulonglong2* hb = (const ulonglong2*)(Hd + k * 34 + r0);
        ulonglong2 hA = hb[0];   // rows r0+0, r0+1 (each {h,h})
        ulonglong2 hB = hb[1];   // rows r0+2, r0+3
        ulonglong2 hC = hb[2];   // rows r0+4, r0+5
        ulonglong2 hD = hb[3];   // rows r0+6, r0+7
        F2(acc[0],  w0, hA.x); F2(acc[1],  w0, hA.y);
        F2(acc[2],  w0, hB.x); F2(acc[3],  w0, hB.y);
        F2(acc[4],  w0, hC.x); F2(acc[5],  w0, hC.y);
        F2(acc[6],  w0, hD.x); F2(acc[7],  w0, hD.y);
        F2(acc[8],  w1, hA.x); F2(acc[9],  w1, hA.y);
        F2(acc[10], w1, hB.x); F2(acc[11], w1, hB.y);
        F2(acc[12], w1, hC.x); F2(acc[13], w1, hC.y);
        F2(acc[14], w1, hD.x); F2(acc[15], w1, hD.y);
        F2(acc[16], w2, hA.x); F2(acc[17], w2, hA.y);
        F2(acc[18], w2, hB.x); F2(acc[19], w2, hB.y);
        F2(acc[20], w2, hC.x); F2(acc[21], w2, hC.y);
        F2(acc[22], w2, hD.x); F2(acc[23], w2, hD.y);
        F2(acc[24], w3, hA.x); F2(acc[25], w3, hA.y);
        F2(acc[26], w3, hB.x); F2(acc[27], w3, hB.y);
        F2(acc[28], w3, hC.x); F2(acc[29], w3, hC.y);
        F2(acc[30], w3, hD.x); F2(acc[31], w3, hD.y);
    }
}

__device__ __forceinline__ void gate_update(const ULL* acc, float* __restrict__ cs,
                                            float2* __restrict__ Hd, int r0, int hh0)
{
#pragma unroll
    for (int r = 0; r < 8; ++r) {
        int row = r0 + r;
        float2 gi = up2(acc[0 * 8 + r]);
        float2 gf = up2(acc[1 * 8 + r]);
        float2 gg = up2(acc[2 * 8 + r]);
        float2 go = up2(acc[3 * 8 + r]);
        float2 c = *(float2*)&cs[row * 128 + hh0];
        float cx = sigm(gf.x) * c.x + sigm(gi.x) * tfast(gg.x);
        float cy = sigm(gf.y) * c.y + sigm(gi.y) * tfast(gg.y);
        float hx = sigm(go.x) * tfast(cx);
        float hy = sigm(go.y) * tfast(cy);
        *(float2*)&cs[row * 128 + hh0] = make_float2(cx, cy);
        Hd[hh0 * 34 + row] = make_float2(hx, hx);
        Hd[(hh0 + 1) * 34 + row] = make_float2(hy, hy);
    }
}

// One full 2-layer timestep for this CTA's 32 rows (thread: 8 rows x 1 gate-pair).
__device__ __forceinline__ void step(SM* sm, const float xv[8][3],
                                     const float* __restrict__ ih0,
                                     const float* __restrict__ b0,
                                     const float* __restrict__ b1,
                                     const float* __restrict__ WThh0,
                                     const float* __restrict__ WTih1,
                                     const float* __restrict__ WThh1,
                                     int r0, int hh0)
{
    ULL acc[32];

    // ---- layer 0 init: bias + Wih0 @ x (input dim 3) ----
#pragma unroll
    for (int g = 0; g < 4; ++g) {
        const int j = g * 128 + hh0;
        ULL bb = *(const ULL*)(b0 + j);
        ULL w0 = *(const ULL*)(ih0 + j);
        ULL w1 = *(const ULL*)(ih0 + 512 + j);
        ULL w2 = *(const ULL*)(ih0 + 1024 + j);
#pragma unroll
        for (int r = 0; r < 8; ++r) {
            ULL a = bb;
            F2(a, w0, pkdup(xv[r][0]));
            F2(a, w1, pkdup(xv[r][1]));
            F2(a, w2, pkdup(xv[r][2]));
            acc[g * 8 + r] = a;
        }
    }
    mv128(WThh0, sm->h0d, r0, hh0, acc);
    __syncthreads();                          // all reads of old h0 done
    gate_update(acc, sm->c0, sm->h0d, r0, hh0);
    __syncthreads();                          // new h0 visible

    // ---- layer 1: bias + Wih1 @ h0_new + Whh1 @ h1_old ----
#pragma unroll
    for (int g = 0; g < 4; ++g) {
        ULL bv = *(const ULL*)(b1 + g * 128 + hh0);
#pragma unroll
        for (int r = 0; r < 8; ++r) acc[g * 8 + r] = bv;
    }
    mv128(WTih1, sm->h0d, r0, hh0, acc);
    mv128(WThh1, sm->h1d, r0, hh0, acc);
    __syncthreads();                          // all reads of old h1 done
    gate_update(acc, sm->c1, sm->h1d, r0, hh0);
    __syncthreads();                          // new h1 visible
}

__global__ void __launch_bounds__(NTH, 2)
lstm_kernel(const float* __restrict__ x,
            const float* __restrict__ fcW, const float* __restrict__ fcb,
            float* __restrict__ out, int B)
{
    extern __shared__ char smraw[];
    SM* sm = (SM*)smraw;

    const int tid = threadIdx.x;
    const int r0 = (tid >> 6) * 8;     // 4 row groups of 8 rows
    const int hh0 = (tid & 63) * 2;    // 64 gate-pair groups
    const int bbase = blockIdx.x * BT;

    // zero duplicated-h and c state; stage fc weights
    for (int i = tid; i < 2 * 128 * 34; i += NTH) sm->h0d[i] = make_float2(0.f, 0.f);
    for (int i = tid; i < 2 * 32 * 128; i += NTH) sm->c0[i] = 0.f;
    for (int i = tid; i < 768; i += NTH) sm->fcWs[i] = fcW[i];
    if (tid < 6) sm->fcbs[tid] = fcb[tid];
    __syncthreads();

    // ---------------- encoder ----------------
    {
        const float* ih0 = g_AUX;                 // e=0
        const float* b0 = g_AUX + 3072;           // e=0, layer 0
        const float* b1 = g_AUX + 3584;           // e=0, layer 1
        for (int t = 0; t < 30; ++t) {
            float xv[8][3];
#pragma unroll
            for (int r = 0; r < 8; ++r) {
                // warp-uniform broadcast loads (r0 is warp-uniform)
                const float* xr = x + (size_t)(bbase + r0 + r) * 90 + 3 * t;
                xv[r][0] = xr[0];
                xv[r][1] = xr[1];
                xv[r][2] = xr[2];
            }
            step(sm, xv, ih0, b0, b1, g_WT[0], g_WT[1], g_WT[2], r0, hh0);
        }
    }

    // seed decoder input with x[:, -1, :]
    if (tid < 96) sm->xcur[(tid / 3) * 4 + (tid % 3)] =
        x[(size_t)(bbase + tid / 3) * 90 + 87 + (tid % 3)];
    __syncthreads();

    // ---------------- decoder ----------------
    const float* ih0 = g_AUX + 1536;              // e=1
    const float* b0 = g_AUX + 4096;               // e=1, layer 0
    const float* b1 = g_AUX + 4608;               // e=1, layer 1
    const size_t logvar_off = (size_t)B * 90;

    for (int t = 0; t < 30; ++t) {
        float xv[8][3];
#pragma unroll
        for (int r = 0; r < 8; ++r) {
            xv[r][0] = sm->xcur[(r0 + r) * 4 + 0];
            xv[r][1] = sm->xcur[(r0 + r) * 4 + 1];
            xv[r][2] = sm->xcur[(r0 + r) * 4 + 2];
        }
        step(sm, xv, ih0, b0, b1, g_WT[3], g_WT[4], g_WT[5], r0, hh0);

        // fc: stats = h1 @ fc_W^T + fc_b  (6 outputs x 32 rows = 192 threads)
        if (tid < 192) {
            int row = tid & 31;
            int o = tid >> 5;       // 0..5
            const float* w = &sm->fcWs[o * 128];
            float s0 = 0.f, s1 = 0.f, s2 = 0.f, s3 = 0.f;
#pragma unroll 8
            for (int k = 0; k < 128; k += 4) {
                s0 += w[k]     * sm->h1d[(k)     * 34 + row].x;
                s1 += w[k + 1] * sm->h1d[(k + 1) * 34 + row].x;
                s2 += w[k + 2] * sm->h1d[(k + 2) * 34 + row].x;
                s3 += w[k + 3] * sm->h1d[(k + 3) * 34 + row].x;
            }
            float s = sm->fcbs[o] + (s0 + s1) + (s2 + s3);
            size_t base = ((size_t)(bbase + row) * 30 + t) * 3;
            if (o < 3) {
                out[base + o] = s;
                sm->xcur[row * 4 + o] = s;   // feedback for next step
            } else {
                out[logvar_off + base + (o - 3)] = s;
            }
        }
        __syncthreads();   // xcur visible for next timestep
    }
}

extern "C" void kernel_launch(void* const* d_in, const int* in_sizes, int n_in,
                              void* d_out, int out_size)
{
    const float* x     = (const float*)d_in[0];
    const float* eWih0 = (const float*)d_in[1];
    const float* eWhh0 = (const float*)d_in[2];
    const float* eb0   = (const float*)d_in[3];
    const float* eWih1 = (const float*)d_in[4];
    const float* eWhh1 = (const float*)d_in[5];
    const float* eb1   = (const float*)d_in[6];
    const float* dWih0 = (const float*)d_in[7];
    const float* dWhh0 = (const float*)d_in[8];
    const float* db0   = (const float*)d_in[9];
    const float* dWih1 = (const float*)d_in[10];
    const float* dWhh1 = (const float*)d_in[11];
    const float* db1   = (const float*)d_in[12];
    const float* fcW   = (const float*)d_in[13];
    const float* fcb   = (const float*)d_in[14];
    float* out = (float*)d_out;

    int B = in_sizes[0] / 90;   // T_IN * IN_DIM = 90

    cudaFuncSetAttribute(lstm_kernel, cudaFuncAttributeMaxDynamicSharedMemorySize,
                         (int)sizeof(SM));

    int prep_n = 6 * 65536 + 5120;
    prep_w<<<(prep_n + 255) / 256, 256>>>(eWhh0, eWih1, eWhh1, dWhh0, dWih1, dWhh1,
                                          eWih0, dWih0, eb0, eb1, db0, db1);

    lstm_kernel<<<B / BT, NTH, sizeof(SM)>>>(x, fcW, fcb, out, B);
}

// round 14
// speedup vs baseline: 1.3389x; 1.3389x over previous
#include <cuda_runtime.h>

#define NTH 256
#define BT  32
typedef unsigned long long ULL;

#define F2(a, b, c) asm("fma.rn.f32x2 %0, %1, %2, %0;" : "+l"(a) : "l"(b), "l"(c))
// 64-thread group barrier (2 warps). ids 1..4; id 0 is __syncthreads().
#define GBAR(id) asm volatile("bar.sync %0, 64;" :: "r"(id) : "memory")

// Pre-transposed weights: [k (128)][j (512)] for LDG.64 pair loads.
// 0: enc_Whh0, 1: enc_Wih1, 2: enc_Whh1, 3: dec_Whh0, 4: dec_Wih1, 5: dec_Whh1
__device__ float g_WT[6][128 * 512];

__global__ void transpose_w(const float* __restrict__ a, const float* __restrict__ b,
                            const float* __restrict__ c, const float* __restrict__ d,
                            const float* __restrict__ e, const float* __restrict__ f)
{
    int idx = blockIdx.x * blockDim.x + threadIdx.x;   // 6 * 65536 total
    int m = idx >> 16;
    int r = idx & 65535;
    int j = r >> 7;       // 0..511
    int k = r & 127;      // 0..127
    const float* src;
    switch (m) {
        case 0: src = a; break;
        case 1: src = b; break;
        case 2: src = c; break;
        case 3: src = d; break;
        case 4: src = e; break;
        default: src = f; break;
    }
    g_WT[m][k * 512 + j] = src[j * 128 + k];
}

struct SM {
    float h0s[32][128];
    float h1s[32][128];
    float c0s[32][128];
    float c1s[32][128];
    float xcur[32][4];
    float wih0s[512 * 3];
    float b0s[512];
    float b1s[512];
    float fcWs[6 * 128];
    float fcbs[8];
};

__device__ __forceinline__ unsigned long long pk2(float lo, float hi) {
    ULL v;
    asm("mov.b64 %0, {%1, %2};" : "=l"(v) : "f"(lo), "f"(hi));
    return v;
}
__device__ __forceinline__ float2 up2(ULL v) {
    float2 f;
    asm("mov.b64 {%0, %1}, %2;" : "=f"(f.x), "=f"(f.y) : "l"(v));
    return f;
}
__device__ __forceinline__ float tfast(float x) {
    float y;
    asm("tanh.approx.f32 %0, %1;" : "=f"(y) : "f"(x));
    return y;
}
__device__ __forceinline__ float sigm(float x) {
    return fmaf(0.5f, tfast(0.5f * x), 0.5f);
}

// acc[g*8 + r]: gate pair (hh0, hh0+1) for row r0+r, gate block g.
// R8-proven inner loop: 4 LDG.64 + 8 LDS.32 + 8 dup-movs + 32 FFMA2, unroll 2.
__device__ __forceinline__ void mv128(const float* __restrict__ WT,
                                      const float (*__restrict__ hs)[128],
                                      int r0, int hh0, ULL* acc)
{
    const float* wp = WT + hh0;
#pragma unroll 2
    for (int k = 0; k < 128; ++k) {
        const float* wk = wp + k * 512;
        ULL w0 = *(const ULL*)(wk);
        ULL w1 = *(const ULL*)(wk + 128);
        ULL w2 = *(const ULL*)(wk + 256);
        ULL w3 = *(const ULL*)(wk + 384);
#pragma unroll
        for (int r = 0; r < 8; ++r) {
            float hv = hs[r0 + r][k];
            ULL hp;
            asm("mov.b64 %0, {%1, %1};" : "=l"(hp) : "f"(hv));
            F2(acc[0 * 8 + r], w0, hp);
            F2(acc[1 * 8 + r], w1, hp);
            F2(acc[2 * 8 + r], w2, hp);
            F2(acc[3 * 8 + r], w3, hp);
        }
    }
}

__device__ __forceinline__ void gate_update(const ULL* acc,
                                            float (*__restrict__ cs)[128],
                                            float (*__restrict__ hsout)[128],
                                            int r0, int hh0)
{
#pragma unroll
    for (int r = 0; r < 8; ++r) {
        float2 gi = up2(acc[0 * 8 + r]);
        float2 gf = up2(acc[1 * 8 + r]);
        float2 gg = up2(acc[2 * 8 + r]);
        float2 go = up2(acc[3 * 8 + r]);
        float2 c = *(float2*)&cs[r0 + r][hh0];
        float cx = sigm(gf.x) * c.x + sigm(gi.x) * tfast(gg.x);
        float cy = sigm(gf.y) * c.y + sigm(gi.y) * tfast(gg.y);
        float hx = sigm(go.x) * tfast(cx);
        float hy = sigm(go.y) * tfast(cy);
        *(float2*)&cs[r0 + r][hh0] = make_float2(cx, cy);
        *(float2*)&hsout[r0 + r][hh0] = make_float2(hx, hy);
    }
}

// One 2-layer timestep. Group-local barriers except the final full sync
// (drift bound so the 4 groups keep sharing weight lines in L1).
__device__ __forceinline__ void step(SM* sm, const float xv[8][3],
                                     const float* __restrict__ WThh0,
                                     const float* __restrict__ WTih1,
                                     const float* __restrict__ WThh1,
                                     int r0, int hh0, int bid)
{
    ULL acc[32];

    // ---- layer 0: bias + Wih0 @ x (input dim 3) ----
#pragma unroll
    for (int g = 0; g < 4; ++g) {
        const int j = g * 128 + hh0;
        const float bl = sm->b0s[j];
        const float bh = sm->b0s[j + 1];
        const float* wl = &sm->wih0s[j * 3];
        float wl0 = wl[0], wl1 = wl[1], wl2 = wl[2];
        float wh0 = wl[3], wh1 = wl[4], wh2 = wl[5];
#pragma unroll
        for (int r = 0; r < 8; ++r) {
            float lo = bl + wl0 * xv[r][0] + wl1 * xv[r][1] + wl2 * xv[r][2];
            float hi = bh + wh0 * xv[r][0] + wh1 * xv[r][1] + wh2 * xv[r][2];
            acc[g * 8 + r] = pk2(lo, hi);
        }
    }
    mv128(WThh0, sm->h0s, r0, hh0, acc);
    GBAR(bid);                              // group done reading old h0 rows
    gate_update(acc, sm->c0s, sm->h0s, r0, hh0);
    GBAR(bid);                              // group's new h0 rows visible

    // ---- layer 1: bias + Wih1 @ h0_new + Whh1 @ h1_old ----
#pragma unroll
    for (int g = 0; g < 4; ++g) {
        const int j = g * 128 + hh0;
        ULL bv = pk2(sm->b1s[j], sm->b1s[j + 1]);
#pragma unroll
        for (int r = 0; r < 8; ++r) acc[g * 8 + r] = bv;
    }
    mv128(WTih1, sm->h0s, r0, hh0, acc);
    mv128(WThh1, sm->h1s, r0, hh0, acc);
    GBAR(bid);                              // group done reading old h1 rows
    gate_update(acc, sm->c1s, sm->h1s, r0, hh0);
    __syncthreads();                        // full sync: h1 visible + drift bound
}

__global__ void __launch_bounds__(NTH, 2)
lstm_kernel(const float* __restrict__ x,
            const float* __restrict__ eWih0, const float* __restrict__ eb0,
            const float* __restrict__ eb1,
            const float* __restrict__ dWih0, const float* __restrict__ db0,
            const float* __restrict__ db1,
            const float* __restrict__ fcW, const float* __restrict__ fcb,
            float* __restrict__ out, int B)
{
    extern __shared__ char smraw[];
    SM* sm = (SM*)smraw;

    const int tid = threadIdx.x;
    const int grp = tid >> 6;             // 0..3 (64-thread group = 2 warps)
    const int bid = grp + 1;              // named barrier id (0 = syncthreads)
    const int r0 = grp * 8;               // this group's 8 rows
    const int hh0 = (tid & 63) * 2;       // gate-pair column
    const int t64 = tid & 63;
    const int bbase = blockIdx.x * BT;

    for (int i = tid; i < 768; i += NTH) sm->fcWs[i] = fcW[i];
    if (tid < 6) sm->fcbs[tid] = fcb[tid];
    for (int i = tid; i < 1536; i += NTH) sm->wih0s[i] = eWih0[i];
    for (int i = tid; i < 512; i += NTH) { sm->b0s[i] = eb0[i]; sm->b1s[i] = eb1[i]; }
#pragma unroll
    for (int r = 0; r < 8; ++r) {
        *(float2*)&sm->h0s[r0 + r][hh0] = make_float2(0.f, 0.f);
        *(float2*)&sm->h1s[r0 + r][hh0] = make_float2(0.f, 0.f);
        *(float2*)&sm->c0s[r0 + r][hh0] = make_float2(0.f, 0.f);
        *(float2*)&sm->c1s[r0 + r][hh0] = make_float2(0.f, 0.f);
    }
    __syncthreads();

    // ---------------- encoder ----------------
    for (int t = 0; t < 30; ++t) {
        float xv[8][3];
#pragma unroll
        for (int r = 0; r < 8; ++r) {
            // warp-uniform broadcast loads; x tile is L1/L2 resident
            const float* xr = x + (size_t)(bbase + r0 + r) * 90 + 3 * t;
            xv[r][0] = xr[0];
            xv[r][1] = xr[1];
            xv[r][2] = xr[2];
        }
        step(sm, xv, g_WT[0], g_WT[1], g_WT[2], r0, hh0, bid);
    }

    // swap in decoder small weights; seed decoder input with x[:, -1, :]
    for (int i = tid; i < 1536; i += NTH) sm->wih0s[i] = dWih0[i];
    for (int i = tid; i < 512; i += NTH) { sm->b0s[i] = db0[i]; sm->b1s[i] = db1[i]; }
    if (tid < 96) sm->xcur[tid / 3][tid % 3] =
        x[(size_t)(bbase + tid / 3) * 90 + 87 + (tid % 3)];
    __syncthreads();

    // ---------------- decoder ----------------
    const size_t logvar_off = (size_t)B * 90;
    for (int t = 0; t < 30; ++t) {
        float xv[8][3];
#pragma unroll
        for (int r = 0; r < 8; ++r) {
            xv[r][0] = sm->xcur[r0 + r][0];
            xv[r][1] = sm->xcur[r0 + r][1];
            xv[r][2] = sm->xcur[r0 + r][2];
        }
        step(sm, xv, g_WT[3], g_WT[4], g_WT[5], r0, hh0, bid);

        // fc: group-local — rows r0..r0+7 handled by this group's 48 of 64 threads
        if (t64 < 48) {
            int row = r0 + t64 / 6;
            int o = t64 % 6;
            const float* w = &sm->fcWs[o * 128];
            const float* hv = sm->h1s[row];
            float s0 = 0.f, s1 = 0.f, s2 = 0.f, s3 = 0.f;
#pragma unroll 8
            for (int k = 0; k < 128; k += 4) {
                s0 += w[k] * hv[k];
                s1 += w[k + 1] * hv[k + 1];
                s2 += w[k + 2] * hv[k + 2];
                s3 += w[k + 3] * hv[k + 3];
            }
            float s = sm->fcbs[o] + (s0 + s1) + (s2 + s3);
            size_t base = ((size_t)(bbase + row) * 30 + t) * 3;
            if (o < 3) {
                out[base + o] = s;
                sm->xcur[row][o] = s;      // feedback, read only by this group
            } else {
                out[logvar_off + base + (o - 3)] = s;
            }
        }
        GBAR(bid);        // xcur rows visible to this group for next timestep
    }
}

extern "C" void kernel_launch(void* const* d_in, const int* in_sizes, int n_in,
                              void* d_out, int out_size)
{
    const float* x     = (const float*)d_in[0];
    const float* eWih0 = (const float*)d_in[1];
    const float* eWhh0 = (const float*)d_in[2];
    const float* eb0   = (const float*)d_in[3];
    const float* eWih1 = (const float*)d_in[4];
    const float* eWhh1 = (const float*)d_in[5];
    const float* eb1   = (const float*)d_in[6];
    const float* dWih0 = (const float*)d_in[7];
    const float* dWhh0 = (const float*)d_in[8];
    const float* db0   = (const float*)d_in[9];
    const float* dWih1 = (const float*)d_in[10];
    const float* dWhh1 = (const float*)d_in[11];
    const float* db1   = (const float*)d_in[12];
    const float* fcW   = (const float*)d_in[13];
    const float* fcb   = (const float*)d_in[14];
    float* out = (float*)d_out;

    int B = in_sizes[0] / 90;   // T_IN * IN_DIM = 90

    cudaFuncSetAttribute(lstm_kernel, cudaFuncAttributeMaxDynamicSharedMemorySize,
                         (int)sizeof(SM));

    // Pre-transpose the six 512x128 matrices to [k][j] layout.
    transpose_w<<<(6 * 65536) / 256, 256>>>(eWhh0, eWih1, eWhh1, dWhh0, dWih1, dWhh1);

    lstm_kernel<<<B / BT, NTH, sizeof(SM)>>>(x, eWih0, eb0, eb1, dWih0, db0, db1,
                                             fcW, fcb, out, B);
}

// round 15
// speedup vs baseline: 1.3391x; 1.0002x over previous
#include <cuda_runtime.h>

#define NTH 256
#define BT  32
typedef unsigned long long ULL;

#define F2(a, b, c) asm("fma.rn.f32x2 %0, %1, %2, %0;" : "+l"(a) : "l"(b), "l"(c))
// 64-thread group barrier (2 warps). ids 1..4; id 0 is __syncthreads().
#define GBAR(id) asm volatile("bar.sync %0, 64;" :: "r"(id) : "memory")

// Pre-transposed weights: [k (128)][j (512)] for LDG.64 pair loads.
// 0: enc_Whh0, 1: enc_Wih1, 2: enc_Whh1, 3: dec_Whh0, 4: dec_Wih1, 5: dec_Whh1
__device__ float g_WT[6][128 * 512];

__global__ void transpose_w(const float* __restrict__ a, const float* __restrict__ b,
                            const float* __restrict__ c, const float* __restrict__ d,
                            const float* __restrict__ e, const float* __restrict__ f)
{
    int idx = blockIdx.x * blockDim.x + threadIdx.x;   // 6 * 65536 total
    int m = idx >> 16;
    int r = idx & 65535;
    int j = r >> 7;       // 0..511
    int k = r & 127;      // 0..127
    const float* src;
    switch (m) {
        case 0: src = a; break;
        case 1: src = b; break;
        case 2: src = c; break;
        case 3: src = d; break;
        case 4: src = e; break;
        default: src = f; break;
    }
    g_WT[m][k * 512 + j] = src[j * 128 + k];
}

struct SM {
    float h0s[32][128];
    float h1s[32][128];
    float c0s[32][128];
    float c1s[32][128];
    float xcur[32][4];
    float wih0s[512 * 3];
    float b0s[512];
    float b1s[512];
    float fcWs[6 * 128];
    float fcbs[8];
};

__device__ __forceinline__ unsigned long long pk2(float lo, float hi) {
    ULL v;
    asm("mov.b64 %0, {%1, %2};" : "=l"(v) : "f"(lo), "f"(hi));
    return v;
}
__device__ __forceinline__ float2 up2(ULL v) {
    float2 f;
    asm("mov.b64 {%0, %1}, %2;" : "=f"(f.x), "=f"(f.y) : "l"(v));
    return f;
}
__device__ __forceinline__ float tfast(float x) {
    float y;
    asm("tanh.approx.f32 %0, %1;" : "=f"(y) : "f"(x));
    return y;
}
__device__ __forceinline__ float sigm(float x) {
    return fmaf(0.5f, tfast(0.5f * x), 0.5f);
}

// acc[g*8 + r]: gate pair (hh0, hh0+1) for row r0+r, gate block g.
// R8-proven inner loop: 4 LDG.64 + 8 LDS.32 + 8 dup-movs + 32 FFMA2, unroll 2.
__device__ __forceinline__ void mv128(const float* __restrict__ WT,
                                      const float (*__restrict__ hs)[128],
                                      int r0, int hh0, ULL* acc)
{
    const float* wp = WT + hh0;
#pragma unroll 2
    for (int k = 0; k < 128; ++k) {
        const float* wk = wp + k * 512;
        ULL w0 = *(const ULL*)(wk);
        ULL w1 = *(const ULL*)(wk + 128);
        ULL w2 = *(const ULL*)(wk + 256);
        ULL w3 = *(const ULL*)(wk + 384);
#pragma unroll
        for (int r = 0; r < 8; ++r) {
            float hv = hs[r0 + r][k];
            ULL hp;
            asm("mov.b64 %0, {%1, %1};" : "=l"(hp) : "f"(hv));
            F2(acc[0 * 8 + r], w0, hp);
            F2(acc[1 * 8 + r], w1, hp);
            F2(acc[2 * 8 + r], w2, hp);
            F2(acc[3 * 8 + r], w3, hp);
        }
    }
}

__device__ __forceinline__ void gate_update(const ULL* acc,
                                            float (*__restrict__ cs)[128],
                                            float (*__restrict__ hsout)[128],
                                            int r0, int hh0)
{
#pragma unroll
    for (int r = 0; r < 8; ++r) {
        float2 gi = up2(acc[0 * 8 + r]);
        float2 gf = up2(acc[1 * 8 + r]);
        float2 gg = up2(acc[2 * 8 + r]);
        float2 go = up2(acc[3 * 8 + r]);
        float2 c = *(float2*)&cs[r0 + r][hh0];
        float cx = sigm(gf.x) * c.x + sigm(gi.x) * tfast(gg.x);
        float cy = sigm(gf.y) * c.y + sigm(gi.y) * tfast(gg.y);
        float hx = sigm(go.x) * tfast(cx);
        float hy = sigm(go.y) * tfast(cy);
        *(float2*)&cs[r0 + r][hh0] = make_float2(cx, cy);
        *(float2*)&hsout[r0 + r][hh0] = make_float2(hx, hy);
    }
}

// One 2-layer timestep. Group-local barriers except the final full sync
// (drift bound so the 4 groups keep sharing weight lines in L1).
__device__ __forceinline__ void step(SM* sm, const float xv[8][3],
                                     const float* __restrict__ WThh0,
                                     const float* __restrict__ WTih1,
                                     const float* __restrict__ WThh1,
                                     int r0, int hh0, int bid)
{
    ULL acc[32];

    // ---- layer 0: bias + Wih0 @ x (input dim 3) ----
#pragma unroll
    for (int g = 0; g < 4; ++g) {
        const int j = g * 128 + hh0;
        const float bl = sm->b0s[j];
        const float bh = sm->b0s[j + 1];
        const float* wl = &sm->wih0s[j * 3];
        float wl0 = wl[0], wl1 = wl[1], wl2 = wl[2];
        float wh0 = wl[3], wh1 = wl[4], wh2 = wl[5];
#pragma unroll
        for (int r = 0; r < 8; ++r) {
            float lo = bl + wl0 * xv[r][0] + wl1 * xv[r][1] + wl2 * xv[r][2];
            float hi = bh + wh0 * xv[r][0] + wh1 * xv[r][1] + wh2 * xv[r][2];
            acc[g * 8 + r] = pk2(lo, hi);
        }
    }
    mv128(WThh0, sm->h0s, r0, hh0, acc);
    GBAR(bid);                              // group done reading old h0 rows
    gate_update(acc, sm->c0s, sm->h0s, r0, hh0);
    GBAR(bid);                              // group's new h0 rows visible

    // ---- layer 1: bias + Wih1 @ h0_new + Whh1 @ h1_old ----
#pragma unroll
    for (int g = 0; g < 4; ++g) {
        const int j = g * 128 + hh0;
        ULL bv = pk2(sm->b1s[j], sm->b1s[j + 1]);
#pragma unroll
        for (int r = 0; r < 8; ++r) acc[g * 8 + r] = bv;
    }
    mv128(WTih1, sm->h0s, r0, hh0, acc);
    mv128(WThh1, sm->h1s, r0, hh0, acc);
    GBAR(bid);                              // group done reading old h1 rows
    gate_update(acc, sm->c1s, sm->h1s, r0, hh0);
    __syncthreads();                        // full sync: h1 visible + drift bound
}

__global__ void __launch_bounds__(NTH, 2)
lstm_kernel(const float* __restrict__ x,
            const float* __restrict__ eWih0, const float* __restrict__ eb0,
            const float* __restrict__ eb1,
            const float* __restrict__ dWih0, const float* __restrict__ db0,
            const float* __restrict__ db1,
            const float* __restrict__ fcW, const float* __restrict__ fcb,
            float* __restrict__ out, int B)
{
    extern __shared__ char smraw[];
    SM* sm = (SM*)smraw;

    const int tid = threadIdx.x;
    const int grp = tid >> 6;             // 0..3 (64-thread group = 2 warps)
    const int bid = grp + 1;              // named barrier id (0 = syncthreads)
    const int r0 = grp * 8;               // this group's 8 rows
    const int hh0 = (tid & 63) * 2;       // gate-pair column
    const int t64 = tid & 63;
    const int bbase = blockIdx.x * BT;

    for (int i = tid; i < 768; i += NTH) sm->fcWs[i] = fcW[i];
    if (tid < 6) sm->fcbs[tid] = fcb[tid];
    for (int i = tid; i < 1536; i += NTH) sm->wih0s[i] = eWih0[i];
    for (int i = tid; i < 512; i += NTH) { sm->b0s[i] = eb0[i]; sm->b1s[i] = eb1[i]; }
#pragma unroll
    for (int r = 0; r < 8; ++r) {
        *(float2*)&sm->h0s[r0 + r][hh0] = make_float2(0.f, 0.f);
        *(float2*)&sm->h1s[r0 + r][hh0] = make_float2(0.f, 0.f);
        *(float2*)&sm->c0s[r0 + r][hh0] = make_float2(0.f, 0.f);
        *(float2*)&sm->c1s[r0 + r][hh0] = make_float2(0.f, 0.f);
    }
    __syncthreads();

    // ---------------- encoder ----------------
    for (int t = 0; t < 30; ++t) {
        float xv[8][3];
#pragma unroll
        for (int r = 0; r < 8; ++r) {
            // warp-uniform broadcast loads; x tile is L1/L2 resident
            const float* xr = x + (size_t)(bbase + r0 + r) * 90 + 3 * t;
            xv[r][0] = xr[0];
            xv[r][1] = xr[1];
            xv[r][2] = xr[2];
        }
        step(sm, xv, g_WT[0], g_WT[1], g_WT[2], r0, hh0, bid);
    }

    // swap in decoder small weights; seed decoder input with x[:, -1, :]
    for (int i = tid; i < 1536; i += NTH) sm->wih0s[i] = dWih0[i];
    for (int i = tid; i < 512; i += NTH) { sm->b0s[i] = db0[i]; sm->b1s[i] = db1[i]; }
    if (tid < 96) sm->xcur[tid / 3][tid % 3] =
        x[(size_t)(bbase + tid / 3) * 90 + 87 + (tid % 3)];
    __syncthreads();

    // ---------------- decoder ----------------
    const size_t logvar_off = (size_t)B * 90;
    for (int t = 0; t < 30; ++t) {
        float xv[8][3];
#pragma unroll
        for (int r = 0; r < 8; ++r) {
            xv[r][0] = sm->xcur[r0 + r][0];
            xv[r][1] = sm->xcur[r0 + r][1];
            xv[r][2] = sm->xcur[r0 + r][2];
        }
        step(sm, xv, g_WT[3], g_WT[4], g_WT[5], r0, hh0, bid);

        // fc: group-local — rows r0..r0+7 handled by this group's 48 of 64 threads
        if (t64 < 48) {
            int row = r0 + t64 / 6;
            int o = t64 % 6;
            const float* w = &sm->fcWs[o * 128];
            const float* hv = sm->h1s[row];
            float s0 = 0.f, s1 = 0.f, s2 = 0.f, s3 = 0.f;
#pragma unroll 8
            for (int k = 0; k < 128; k += 4) {
                s0 += w[k] * hv[k];
                s1 += w[k + 1] * hv[k + 1];
                s2 += w[k + 2] * hv[k + 2];
                s3 += w[k + 3] * hv[k + 3];
            }
            float s = sm->fcbs[o] + (s0 + s1) + (s2 + s3);
            size_t base = ((size_t)(bbase + row) * 30 + t) * 3;
            if (o < 3) {
                out[base + o] = s;
                sm->xcur[row][o] = s;      // feedback, read only by this group
            } else {
                out[logvar_off + base + (o - 3)] = s;
            }
        }
        GBAR(bid);        // xcur rows visible to this group for next timestep
    }
}

extern "C" void kernel_launch(void* const* d_in, const int* in_sizes, int n_in,
                              void* d_out, int out_size)
{
    const float* x     = (const float*)d_in[0];
    const float* eWih0 = (const float*)d_in[1];
    const float* eWhh0 = (const float*)d_in[2];
    const float* eb0   = (const float*)d_in[3];
    const float* eWih1 = (const float*)d_in[4];
    const float* eWhh1 = (const float*)d_in[5];
    const float* eb1   = (const float*)d_in[6];
    const float* dWih0 = (const float*)d_in[7];
    const float* dWhh0 = (const float*)d_in[8];
    const float* db0   = (const float*)d_in[9];
    const float* dWih1 = (const float*)d_in[10];
    const float* dWhh1 = (const float*)d_in[11];
    const float* db1   = (const float*)d_in[12];
    const float* fcW   = (const float*)d_in[13];
    const float* fcb   = (const float*)d_in[14];
    float* out = (float*)d_out;

    int B = in_sizes[0] / 90;   // T_IN * IN_DIM = 90

    cudaFuncSetAttribute(lstm_kernel, cudaFuncAttributeMaxDynamicSharedMemorySize,
                         (int)sizeof(SM));

    // Pre-transpose the six 512x128 matrices to [k][j] layout.
    transpose_w<<<(6 * 65536) / 256, 256>>>(eWhh0, eWih1, eWhh1, dWhh0, dWih1, dWhh1);

    lstm_kernel<<<B / BT, NTH, sizeof(SM)>>>(x, eWih0, eb0, eb1, dWih0, db0, db1,
                                             fcW, fcb, out, B);
}

// round 16
// speedup vs baseline: 1.3393x; 1.0001x over previous
#include <cuda_runtime.h>

#define NTH 256
#define BT  32
typedef unsigned long long ULL;

#define F2(a, b, c) asm("fma.rn.f32x2 %0, %1, %2, %0;" : "+l"(a) : "l"(b), "l"(c))
// 64-thread group barrier (2 warps). ids 1..4; id 0 is __syncthreads().
#define GBAR(id) asm volatile("bar.sync %0, 64;" :: "r"(id) : "memory")

// Pre-transposed weights: [k (128)][j (512)] for LDG.64 pair loads.
// 0: enc_Whh0, 1: enc_Wih1, 2: enc_Whh1, 3: dec_Whh0, 4: dec_Wih1, 5: dec_Whh1
__device__ float g_WT[6][128 * 512];

__global__ void transpose_w(const float* __restrict__ a, const float* __restrict__ b,
                            const float* __restrict__ c, const float* __restrict__ d,
                            const float* __restrict__ e, const float* __restrict__ f)
{
    int idx = blockIdx.x * blockDim.x + threadIdx.x;   // 6 * 65536 total
    int m = idx >> 16;
    int r = idx & 65535;
    int j = r >> 7;       // 0..511
    int k = r & 127;      // 0..127
    const float* src;
    switch (m) {
        case 0: src = a; break;
        case 1: src = b; break;
        case 2: src = c; break;
        case 3: src = d; break;
        case 4: src = e; break;
        default: src = f; break;
    }
    g_WT[m][k * 512 + j] = src[j * 128 + k];
}

struct SM {
    float h0s[32][128];
    float h1s[32][128];
    float c0s[32][128];
    float c1s[32][128];
    float xcur[32][4];
    float wih0s[512 * 3];
    float b0s[512];
    float b1s[512];
    float fcWs[6 * 128];
    float fcbs[8];
};

__device__ __forceinline__ unsigned long long pk2(float lo, float hi) {
    ULL v;
    asm("mov.b64 %0, {%1, %2};" : "=l"(v) : "f"(lo), "f"(hi));
    return v;
}
__device__ __forceinline__ float2 up2(ULL v) {
    float2 f;
    asm("mov.b64 {%0, %1}, %2;" : "=f"(f.x), "=f"(f.y) : "l"(v));
    return f;
}
__device__ __forceinline__ float tfast(float x) {
    float y;
    asm("tanh.approx.f32 %0, %1;" : "=f"(y) : "f"(x));
    return y;
}
__device__ __forceinline__ float sigm(float x) {
    return fmaf(0.5f, tfast(0.5f * x), 0.5f);
}

// acc[g*8 + r]: gate pair (hh0, hh0+1) for row r0+r, gate block g.
// R8-proven inner loop: 4 LDG.64 + 8 LDS.32 + 8 dup-movs + 32 FFMA2, unroll 2.
__device__ __forceinline__ void mv128(const float* __restrict__ WT,
                                      const float (*__restrict__ hs)[128],
                                      int r0, int hh0, ULL* acc)
{
    const float* wp = WT + hh0;
#pragma unroll 2
    for (int k = 0; k < 128; ++k) {
        const float* wk = wp + k * 512;
        ULL w0 = *(const ULL*)(wk);
        ULL w1 = *(const ULL*)(wk + 128);
        ULL w2 = *(const ULL*)(wk + 256);
        ULL w3 = *(const ULL*)(wk + 384);
#pragma unroll
        for (int r = 0; r < 8; ++r) {
            float hv = hs[r0 + r][k];
            ULL hp;
            asm("mov.b64 %0, {%1, %1};" : "=l"(hp) : "f"(hv));
            F2(acc[0 * 8 + r], w0, hp);
            F2(acc[1 * 8 + r], w1, hp);
            F2(acc[2 * 8 + r], w2, hp);
            F2(acc[3 * 8 + r], w3, hp);
        }
    }
}

__device__ __forceinline__ void gate_update(const ULL* acc,
                                            float (*__restrict__ cs)[128],
                                            float (*__restrict__ hsout)[128],
                                            int r0, int hh0)
{
#pragma unroll
    for (int r = 0; r < 8; ++r) {
        float2 gi = up2(acc[0 * 8 + r]);
        float2 gf = up2(acc[1 * 8 + r]);
        float2 gg = up2(acc[2 * 8 + r]);
        float2 go = up2(acc[3 * 8 + r]);
        float2 c = *(float2*)&cs[r0 + r][hh0];
        float cx = sigm(gf.x) * c.x + sigm(gi.x) * tfast(gg.x);
        float cy = sigm(gf.y) * c.y + sigm(gi.y) * tfast(gg.y);
        float hx = sigm(go.x) * tfast(cx);
        float hy = sigm(go.y) * tfast(cy);
        *(float2*)&cs[r0 + r][hh0] = make_float2(cx, cy);
        *(float2*)&hsout[r0 + r][hh0] = make_float2(hx, hy);
    }
}

// One 2-layer timestep. Group-local barriers except the final full sync
// (drift bound so the 4 groups keep sharing weight lines in L1).
__device__ __forceinline__ void step(SM* sm, const float xv[8][3],
                                     const float* __restrict__ WThh0,
                                     const float* __restrict__ WTih1,
                                     const float* __restrict__ WThh1,
                                     int r0, int hh0, int bid)
{
    ULL acc[32];

    // ---- layer 0: bias + Wih0 @ x (input dim 3) ----
#pragma unroll
    for (int g = 0; g < 4; ++g) {
        const int j = g * 128 + hh0;
        const float bl = sm->b0s[j];
        const float bh = sm->b0s[j + 1];
        const float* wl = &sm->wih0s[j * 3];
        float wl0 = wl[0], wl1 = wl[1], wl2 = wl[2];
        float wh0 = wl[3], wh1 = wl[4], wh2 = wl[5];
#pragma unroll
        for (int r = 0; r < 8; ++r) {
            float lo = bl + wl0 * xv[r][0] + wl1 * xv[r][1] + wl2 * xv[r][2];
            float hi = bh + wh0 * xv[r][0] + wh1 * xv[r][1] + wh2 * xv[r][2];
            acc[g * 8 + r] = pk2(lo, hi);
        }
    }
    mv128(WThh0, sm->h0s, r0, hh0, acc);
    GBAR(bid);                              // group done reading old h0 rows
    gate_update(acc, sm->c0s, sm->h0s, r0, hh0);
    GBAR(bid);                              // group's new h0 rows visible

    // ---- layer 1: bias + Wih1 @ h0_new + Whh1 @ h1_old ----
#pragma unroll
    for (int g = 0; g < 4; ++g) {
        const int j = g * 128 + hh0;
        ULL bv = pk2(sm->b1s[j], sm->b1s[j + 1]);
#pragma unroll
        for (int r = 0; r < 8; ++r) acc[g * 8 + r] = bv;
    }
    mv128(WTih1, sm->h0s, r0, hh0, acc);
    mv128(WThh1, sm->h1s, r0, hh0, acc);
    GBAR(bid);                              // group done reading old h1 rows
    gate_update(acc, sm->c1s, sm->h1s, r0, hh0);
    __syncthreads();                        // full sync: h1 visible + drift bound
}

__global__ void __launch_bounds__(NTH, 2)
lstm_kernel(const float* __restrict__ x,
            const float* __restrict__ eWih0, const float* __restrict__ eb0,
            const float* __restrict__ eb1,
            const float* __restrict__ dWih0, const float* __restrict__ db0,
            const float* __restrict__ db1,
            const float* __restrict__ fcW, const float* __restrict__ fcb,
            float* __restrict__ out, int B)
{
    extern __shared__ char smraw[];
    SM* sm = (SM*)smraw;

    const int tid = threadIdx.x;
    const int grp = tid >> 6;             // 0..3 (64-thread group = 2 warps)
    const int bid = grp + 1;              // named barrier id (0 = syncthreads)
    const int r0 = grp * 8;               // this group's 8 rows
    const int hh0 = (tid & 63) * 2;       // gate-pair column
    const int t64 = tid & 63;
    const int bbase = blockIdx.x * BT;

    for (int i = tid; i < 768; i += NTH) sm->fcWs[i] = fcW[i];
    if (tid < 6) sm->fcbs[tid] = fcb[tid];
    for (int i = tid; i < 1536; i += NTH) sm->wih0s[i] = eWih0[i];
    for (int i = tid; i < 512; i += NTH) { sm->b0s[i] = eb0[i]; sm->b1s[i] = eb1[i]; }
#pragma unroll
    for (int r = 0; r < 8; ++r) {
        *(float2*)&sm->h0s[r0 + r][hh0] = make_float2(0.f, 0.f);
        *(float2*)&sm->h1s[r0 + r][hh0] = make_float2(0.f, 0.f);
        *(float2*)&sm->c0s[r0 + r][hh0] = make_float2(0.f, 0.f);
        *(float2*)&sm->c1s[r0 + r][hh0] = make_float2(0.f, 0.f);
    }
    __syncthreads();

    // ---------------- encoder ----------------
    for (int t = 0; t < 30; ++t) {
        float xv[8][3];
#pragma unroll
        for (int r = 0; r < 8; ++r) {
            // warp-uniform broadcast loads; x tile is L1/L2 resident
            const float* xr = x + (size_t)(bbase + r0 + r) * 90 + 3 * t;
            xv[r][0] = xr[0];
            xv[r][1] = xr[1];
            xv[r][2] = xr[2];
        }
        step(sm, xv, g_WT[0], g_WT[1], g_WT[2], r0, hh0, bid);
    }

    // swap in decoder small weights; seed decoder input with x[:, -1, :]
    for (int i = tid; i < 1536; i += NTH) sm->wih0s[i] = dWih0[i];
    for (int i = tid; i < 512; i += NTH) { sm->b0s[i] = db0[i]; sm->b1s[i] = db1[i]; }
    if (tid < 96) sm->xcur[tid / 3][tid % 3] =
        x[(size_t)(bbase + tid / 3) * 90 + 87 + (tid % 3)];
    __syncthreads();

    // ---------------- decoder ----------------
    const size_t logvar_off = (size_t)B * 90;
    for (int t = 0; t < 30; ++t) {
        float xv[8][3];
#pragma unroll
        for (int r = 0; r < 8; ++r) {
            xv[r][0] = sm->xcur[r0 + r][0];
            xv[r][1] = sm->xcur[r0 + r][1];
            xv[r][2] = sm->xcur[r0 + r][2];
        }
        step(sm, xv, g_WT[3], g_WT[4], g_WT[5], r0, hh0, bid);

        // fc: group-local — rows r0..r0+7 handled by this group's 48 of 64 threads
        if (t64 < 48) {
            int row = r0 + t64 / 6;
            int o = t64 % 6;
            const float* w = &sm->fcWs[o * 128];
            const float* hv = sm->h1s[row];
            float s0 = 0.f, s1 = 0.f, s2 = 0.f, s3 = 0.f;
#pragma unroll 8
            for (int k = 0; k < 128; k += 4) {
                s0 += w[k] * hv[k];
                s1 += w[k + 1] * hv[k + 1];
                s2 += w[k + 2] * hv[k + 2];
                s3 += w[k + 3] * hv[k + 3];
            }
            float s = sm->fcbs[o] + (s0 + s1) + (s2 + s3);
            size_t base = ((size_t)(bbase + row) * 30 + t) * 3;
            if (o < 3) {
                out[base + o] = s;
                sm->xcur[row][o] = s;      // feedback, read only by this group
            } else {
                out[logvar_off + base + (o - 3)] = s;
            }
        }
        GBAR(bid);        // xcur rows visible to this group for next timestep
    }
}

extern "C" void kernel_launch(void* const* d_in, const int* in_sizes, int n_in,
                              void* d_out, int out_size)
{
    const float* x     = (const float*)d_in[0];
    const float* eWih0 = (const float*)d_in[1];
    const float* eWhh0 = (const float*)d_in[2];
    const float* eb0   = (const float*)d_in[3];
    const float* eWih1 = (const float*)d_in[4];
    const float* eWhh1 = (const float*)d_in[5];
    const float* eb1   = (const float*)d_in[6];
    const float* dWih0 = (const float*)d_in[7];
    const float* dWhh0 = (const float*)d_in[8];
    const float* db0   = (const float*)d_in[9];
    const float* dWih1 = (const float*)d_in[10];
    const float* dWhh1 = (const float*)d_in[11];
    const float* db1   = (const float*)d_in[12];
    const float* fcW   = (const float*)d_in[13];
    const float* fcb   = (const float*)d_in[14];
    float* out = (float*)d_out;

    int B = in_sizes[0] / 90;   // T_IN * IN_DIM = 90

    cudaFuncSetAttribute(lstm_kernel, cudaFuncAttributeMaxDynamicSharedMemorySize,
                         (int)sizeof(SM));

    // Pre-transpose the six 512x128 matrices to [k][j] layout.
    transpose_w<<<(6 * 65536) / 256, 256>>>(eWhh0, eWih1, eWhh1, dWhh0, dWih1, dWhh1);

    lstm_kernel<<<B / BT, NTH, sizeof(SM)>>>(x, eWih0, eb0, eb1, dWih0, db0, db1,
                                             fcW, fcb, out, B);
}